// round 1
// baseline (speedup 1.0000x reference)
#include <cuda_runtime.h>
#include <cstdint>

#define NN 100000
#define EE 1600000
#define HH 128
#define GG 256
#define CC 16
#define KK 2

// ---------------- device scratch (static, allowed) ----------------
__device__ float g_xs[(size_t)NN * HH];   // dis-scaled transformed features
__device__ float g_h [(size_t)NN * HH];   // layer output (pre-BN relu activations)
__device__ float g_dis[NN];
__device__ int   g_deg[NN];
__device__ int   g_rowptr[NN + 1];
__device__ int   g_cursor[NN];
__device__ int   g_csrc[EE];
__device__ float g_stats[2 * HH];         // [0..127] sum, [128..255] sumsq
__device__ float g_bns[HH];               // BN affine scale
__device__ float g_bnt[HH];               // BN affine shift
__device__ float g_pool[GG * HH];
__device__ float g_cnt[GG];
__device__ int   g_i64;                   // 1 if index tensors are int64

__device__ __forceinline__ long long idx_at(const void* p, long long i) {
    if (g_i64) return ((const long long*)p)[i];
    return (long long)((const int*)p)[i];
}

// ---------------- index width detection ----------------
__global__ void k_detect(const int* ei) {
    int lane = threadIdx.x;
    int v = ei[2 * lane + 1] | ei[2 * (lane + 32) + 1] |
            ei[2 * (lane + 64) + 1] | ei[2 * (lane + 96) + 1];
    unsigned m = __ballot_sync(0xffffffffu, v != 0);
    if (lane == 0) g_i64 = (m == 0) ? 1 : 0;
}

// ---------------- init ----------------
__global__ void k_zero_init() {
    int i = blockIdx.x * 256 + threadIdx.x;
    if (i < NN) g_deg[i] = 0;
    if (i < GG * HH) g_pool[i] = 0.f;
    if (i < GG) g_cnt[i] = 0.f;
}

__global__ void k_zero_stats() {
    g_stats[threadIdx.x] = 0.f;
}

// ---------------- CSR build ----------------
__global__ void k_hist(const void* ei) {
    int e = blockIdx.x * 256 + threadIdx.x;
    if (e < EE) {
        int d = (int)idx_at(ei, (long long)EE + e);
        atomicAdd(&g_deg[d], 1);
    }
}

// exclusive scan of g_deg into g_rowptr/g_cursor, single block of 1024, 4 elems/thread
__global__ void k_scan() {
    __shared__ int s[1024];
    __shared__ int carry_s;
    int tid = threadIdx.x;
    if (tid == 0) carry_s = 0;
    __syncthreads();
    for (int base = 0; base < NN; base += 4096) {
        int idx = base + tid * 4;
        int v0 = (idx + 0 < NN) ? g_deg[idx + 0] : 0;
        int v1 = (idx + 1 < NN) ? g_deg[idx + 1] : 0;
        int v2 = (idx + 2 < NN) ? g_deg[idx + 2] : 0;
        int v3 = (idx + 3 < NN) ? g_deg[idx + 3] : 0;
        int tsum = v0 + v1 + v2 + v3;
        s[tid] = tsum;
        __syncthreads();
        // Hillis-Steele inclusive scan
        for (int d = 1; d < 1024; d <<= 1) {
            int t = (tid >= d) ? s[tid - d] : 0;
            __syncthreads();
            s[tid] += t;
            __syncthreads();
        }
        int inc = s[tid];
        int total = s[1023];
        int carry = carry_s;
        int run = carry + inc - tsum;   // exclusive prefix of this thread's group
        if (idx + 0 < NN) { g_rowptr[idx + 0] = run; g_cursor[idx + 0] = run; } run += v0;
        if (idx + 1 < NN) { g_rowptr[idx + 1] = run; g_cursor[idx + 1] = run; } run += v1;
        if (idx + 2 < NN) { g_rowptr[idx + 2] = run; g_cursor[idx + 2] = run; } run += v2;
        if (idx + 3 < NN) { g_rowptr[idx + 3] = run; g_cursor[idx + 3] = run; }
        __syncthreads();
        if (tid == 0) carry_s = carry + total;
        __syncthreads();
    }
    if (tid == 0) g_rowptr[NN] = carry_s;
}

__global__ void k_dis_cnt(const void* batch) {
    int i = blockIdx.x * 256 + threadIdx.x;
    if (i < NN) {
        g_dis[i] = rsqrtf((float)g_deg[i] + 1.0f);
        int g = (int)idx_at(batch, i);
        atomicAdd(&g_cnt[g], 1.0f);
    }
}

__global__ void k_place(const void* ei) {
    int e = blockIdx.x * 256 + threadIdx.x;
    if (e < EE) {
        int d = (int)idx_at(ei, (long long)EE + e);
        int pos = atomicAdd(&g_cursor[d], 1);
        g_csrc[pos] = (int)idx_at(ei, (long long)e);
    }
}

// ---------------- GEMM: xs = dis * ((A[*affine]) @ W), 128x128 tile ----------------
template<bool AFF>
__global__ void __launch_bounds__(256) k_gemm(const float* __restrict__ Ain,
                                              const float* __restrict__ W) {
    __shared__ float As[16][132];   // transposed: As[k][row], padded (132*4B = 33*16B)
    __shared__ float Ws[16][128];
    __shared__ float ss[HH], tt[HH];
    const float* __restrict__ A = AFF ? (const float*)g_h : Ain;
    int tid = threadIdx.x;
    if (AFF && tid < HH) { ss[tid] = g_bns[tid]; tt[tid] = g_bnt[tid]; }
    __syncthreads();

    int rbase = blockIdx.x * 128;
    int tr = (tid >> 4) << 3;   // row offset of 8x8 microtile
    int tc = (tid & 15) << 3;   // col offset

    float c[8][8];
#pragma unroll
    for (int i = 0; i < 8; i++)
#pragma unroll
        for (int j = 0; j < 8; j++) c[i][j] = 0.f;

    for (int kk = 0; kk < HH; kk += 16) {
#pragma unroll
        for (int q = 0; q < 2; q++) {
            int slot = q * 256 + tid;
            // A tile: 128 rows x 16 cols = 512 float4 slots
            int row = slot >> 2, ch = slot & 3;
            int grow = rbase + row;
            float4 v = make_float4(0.f, 0.f, 0.f, 0.f);
            if (grow < NN)
                v = *(const float4*)&A[(size_t)grow * HH + kk + ch * 4];
            int c0 = kk + ch * 4;
            if (AFF) {
                v.x = fmaf(v.x, ss[c0 + 0], tt[c0 + 0]);
                v.y = fmaf(v.y, ss[c0 + 1], tt[c0 + 1]);
                v.z = fmaf(v.z, ss[c0 + 2], tt[c0 + 2]);
                v.w = fmaf(v.w, ss[c0 + 3], tt[c0 + 3]);
            }
            As[ch * 4 + 0][row] = v.x;
            As[ch * 4 + 1][row] = v.y;
            As[ch * 4 + 2][row] = v.z;
            As[ch * 4 + 3][row] = v.w;
            // W tile: 16 rows x 128 cols = 512 float4 slots
            int kr = slot >> 5, cc2 = slot & 31;
            *(float4*)&Ws[kr][cc2 * 4] =
                *(const float4*)&W[(size_t)(kk + kr) * HH + cc2 * 4];
        }
        __syncthreads();
#pragma unroll
        for (int k = 0; k < 16; k++) {
            float a[8], b[8];
            *(float4*)&a[0] = *(float4*)&As[k][tr];
            *(float4*)&a[4] = *(float4*)&As[k][tr + 4];
            *(float4*)&b[0] = *(float4*)&Ws[k][tc];
            *(float4*)&b[4] = *(float4*)&Ws[k][tc + 4];
#pragma unroll
            for (int i = 0; i < 8; i++)
#pragma unroll
                for (int j = 0; j < 8; j++)
                    c[i][j] = fmaf(a[i], b[j], c[i][j]);
        }
        __syncthreads();
    }
#pragma unroll
    for (int i = 0; i < 8; i++) {
        int r = rbase + tr + i;
        if (r < NN) {
            float d = g_dis[r];
            float4 o0 = make_float4(d * c[i][0], d * c[i][1], d * c[i][2], d * c[i][3]);
            float4 o1 = make_float4(d * c[i][4], d * c[i][5], d * c[i][6], d * c[i][7]);
            *(float4*)&g_xs[(size_t)r * HH + tc] = o0;
            *(float4*)&g_xs[(size_t)r * HH + tc + 4] = o1;
        }
    }
}

// ---------------- aggregation + relu + BN stats (+ pooling on last layer) ----------------
template<bool LAST>
__global__ void __launch_bounds__(256) k_agg(const float* __restrict__ bias,
                                             const void* __restrict__ batch) {
    int tid = threadIdx.x;
    int wid = tid >> 5, lane = tid & 31;
    float4 b4 = ((const float4*)bias)[lane];
    float s0 = 0.f, s1 = 0.f, s2 = 0.f, s3 = 0.f;
    float q0 = 0.f, q1 = 0.f, q2 = 0.f, q3 = 0.f;

    for (long long i = (long long)blockIdx.x * 8 + wid; i < NN;
         i += (long long)gridDim.x * 8) {
        const float4* xsv = (const float4*)g_xs;
        float4 acc = xsv[i * 32 + lane];          // self term (dis^2*xw = dis*xs)
        int e0 = g_rowptr[i], e1 = g_rowptr[i + 1];
        for (int e = e0; e < e1; e++) {
            int s = g_csrc[e];
            float4 v = xsv[(long long)s * 32 + lane];
            acc.x += v.x; acc.y += v.y; acc.z += v.z; acc.w += v.w;
        }
        float d = g_dis[i];
        float4 y;
        y.x = fmaxf(fmaf(d, acc.x, b4.x), 0.f);
        y.y = fmaxf(fmaf(d, acc.y, b4.y), 0.f);
        y.z = fmaxf(fmaf(d, acc.z, b4.z), 0.f);
        y.w = fmaxf(fmaf(d, acc.w, b4.w), 0.f);
        if (!LAST) {
            ((float4*)g_h)[i * 32 + lane] = y;
        } else {
            int g = (int)idx_at(batch, i);
            float* p = &g_pool[g * HH + lane * 4];
            atomicAdd(p + 0, y.x);
            atomicAdd(p + 1, y.y);
            atomicAdd(p + 2, y.z);
            atomicAdd(p + 3, y.w);
        }
        s0 += y.x; s1 += y.y; s2 += y.z; s3 += y.w;
        q0 += y.x * y.x; q1 += y.y * y.y; q2 += y.z * y.z; q3 += y.w * y.w;
    }
    __shared__ float red[2 * HH];
    red[tid] = 0.f;
    __syncthreads();
    atomicAdd(&red[lane * 4 + 0], s0);
    atomicAdd(&red[lane * 4 + 1], s1);
    atomicAdd(&red[lane * 4 + 2], s2);
    atomicAdd(&red[lane * 4 + 3], s3);
    atomicAdd(&red[HH + lane * 4 + 0], q0);
    atomicAdd(&red[HH + lane * 4 + 1], q1);
    atomicAdd(&red[HH + lane * 4 + 2], q2);
    atomicAdd(&red[HH + lane * 4 + 3], q3);
    __syncthreads();
    atomicAdd(&g_stats[tid], red[tid]);
}

// ---------------- BN stats -> affine ----------------
__global__ void k_stats(const float* __restrict__ gamma, const float* __restrict__ beta) {
    int f = threadIdx.x;
    float m = g_stats[f] * (1.0f / NN);
    float v = g_stats[HH + f] * (1.0f / NN) - m * m;
    v = fmaxf(v, 0.f);
    float s = gamma[f] * rsqrtf(v + 1e-5f);
    g_bns[f] = s;
    g_bnt[f] = beta[f] - m * s;
}

// ---------------- final head: pooled(BN3) ++ clinical -> linear ----------------
__global__ void k_final(const float* __restrict__ clinical,
                        const float* __restrict__ Wc,
                        const float* __restrict__ bc,
                        float* __restrict__ out) {
    int g = blockIdx.x, j = threadIdx.x;   // 128 threads
    float cnt = fmaxf(g_cnt[g], 1.0f);
    float p = g_pool[g * HH + j] / cnt;
    p = fmaf(p, g_bns[j], g_bnt[j]);
    float r0 = p * Wc[j * KK + 0];
    float r1 = p * Wc[j * KK + 1];
    if (j < CC) {
        float cl = clinical[g * CC + j];
        r0 = fmaf(cl, Wc[(HH + j) * KK + 0], r0);
        r1 = fmaf(cl, Wc[(HH + j) * KK + 1], r1);
    }
    __shared__ float sm0[128], sm1[128];
    sm0[j] = r0; sm1[j] = r1;
    __syncthreads();
    for (int d = 64; d > 0; d >>= 1) {
        if (j < d) { sm0[j] += sm0[j + d]; sm1[j] += sm1[j + d]; }
        __syncthreads();
    }
    if (j == 0) {
        out[g * KK + 0] = sm0[0] + bc[0];
        out[g * KK + 1] = sm1[0] + bc[1];
    }
}

// ---------------- launch ----------------
extern "C" void kernel_launch(void* const* d_in, const int* in_sizes, int n_in,
                              void* d_out, int out_size) {
    const float* x        = (const float*)d_in[0];
    const void*  ei       = d_in[1];
    const void*  batch    = d_in[2];
    const float* clinical = (const float*)d_in[3];
    const float* W1 = (const float*)d_in[4];  const float* b1 = (const float*)d_in[5];
    const float* W2 = (const float*)d_in[6];  const float* b2 = (const float*)d_in[7];
    const float* W3 = (const float*)d_in[8];  const float* b3 = (const float*)d_in[9];
    const float* g1 = (const float*)d_in[10]; const float* be1 = (const float*)d_in[11];
    const float* g2 = (const float*)d_in[12]; const float* be2 = (const float*)d_in[13];
    const float* g3 = (const float*)d_in[14]; const float* be3 = (const float*)d_in[15];
    const float* Wc = (const float*)d_in[16]; const float* bc = (const float*)d_in[17];
    float* out = (float*)d_out;

    const int gemm_blocks = (NN + 127) / 128;   // 782
    const int e_blocks    = (EE + 255) / 256;   // 6250
    const int n_blocks    = (NN + 255) / 256;   // 391

    k_detect<<<1, 32>>>((const int*)ei);
    k_zero_init<<<n_blocks, 256>>>();
    k_hist<<<e_blocks, 256>>>(ei);
    k_scan<<<1, 1024>>>();
    k_dis_cnt<<<n_blocks, 256>>>(batch);
    k_place<<<e_blocks, 256>>>(ei);

    // layer 1
    k_zero_stats<<<1, 256>>>();
    k_gemm<false><<<gemm_blocks, 256>>>(x, W1);
    k_agg<false><<<1024, 256>>>(b1, batch);
    k_stats<<<1, 128>>>(g1, be1);

    // layer 2
    k_zero_stats<<<1, 256>>>();
    k_gemm<true><<<gemm_blocks, 256>>>(nullptr, W2);
    k_agg<false><<<1024, 256>>>(b2, batch);
    k_stats<<<1, 128>>>(g2, be2);

    // layer 3
    k_zero_stats<<<1, 256>>>();
    k_gemm<true><<<gemm_blocks, 256>>>(nullptr, W3);
    k_agg<true><<<1024, 256>>>(b3, batch);
    k_stats<<<1, 128>>>(g3, be3);

    k_final<<<GG, 128>>>(clinical, Wc, bc, out);
}

// round 2
// speedup vs baseline: 1.2804x; 1.2804x over previous
#include <cuda_runtime.h>
#include <cstdint>

#define NN 100000
#define EE 1600000
#define HH 128
#define GG 256
#define CC 16
#define KK 2

#define SCAN_BLOCKS ((NN + 255) / 256)   // 391

// ---------------- device scratch (static, allowed) ----------------
__device__ float g_xs[(size_t)NN * HH];   // dis-scaled transformed features
__device__ float g_h [(size_t)NN * HH];   // layer output (post relu activations)
__device__ float g_dis[NN];
__device__ int   g_deg[NN];
__device__ int   g_rowptr[NN + 1];
__device__ int   g_cursor[NN];
__device__ int   g_csrc[EE];
__device__ float g_stats[2 * HH];         // [0..127] sum, [128..255] sumsq
__device__ float g_bns[HH];               // BN affine scale
__device__ float g_bnt[HH];               // BN affine shift
__device__ float g_pool[GG * HH];
__device__ float g_cnt[GG];
__device__ int   g_i64;                   // 1 if index tensors are int64
__device__ int   g_blk[SCAN_BLOCKS + 8];
__device__ int   g_blkoff[SCAN_BLOCKS + 8];
__device__ uint32_t g_wth[HH * HH];       // W^T hi (tf32 bits), layout [n][k]
__device__ uint32_t g_wtl[HH * HH];       // W^T lo (fp32 bits)

__device__ __forceinline__ long long idx_at(const void* p, long long i) {
    if (g_i64) return ((const long long*)p)[i];
    return (long long)((const int*)p)[i];
}

__device__ __forceinline__ uint32_t f2tf32(float x) {
    uint32_t r;
    asm("cvt.rna.tf32.f32 %0, %1;" : "=r"(r) : "f"(x));
    return r;
}

__device__ __forceinline__ void mma_tf32(float* c, const uint32_t* a,
                                         uint32_t b0, uint32_t b1) {
    asm volatile(
        "mma.sync.aligned.m16n8k8.row.col.f32.tf32.tf32.f32 "
        "{%0,%1,%2,%3}, {%4,%5,%6,%7}, {%8,%9}, {%0,%1,%2,%3};\n"
        : "+f"(c[0]), "+f"(c[1]), "+f"(c[2]), "+f"(c[3])
        : "r"(a[0]), "r"(a[1]), "r"(a[2]), "r"(a[3]), "r"(b0), "r"(b1));
}

// ---------------- index width detection ----------------
__global__ void k_detect(const int* ei) {
    int lane = threadIdx.x;
    int v = ei[2 * lane + 1] | ei[2 * (lane + 32) + 1] |
            ei[2 * (lane + 64) + 1] | ei[2 * (lane + 96) + 1];
    unsigned m = __ballot_sync(0xffffffffu, v != 0);
    if (lane == 0) g_i64 = (m == 0) ? 1 : 0;
}

// ---------------- init ----------------
__global__ void k_zero_init() {
    int i = blockIdx.x * 256 + threadIdx.x;
    if (i < NN) g_deg[i] = 0;
    if (i < GG * HH) g_pool[i] = 0.f;
    if (i < GG) g_cnt[i] = 0.f;
    if (i < 2 * HH) g_stats[i] = 0.f;
}

// ---------------- CSR build ----------------
__global__ void k_hist(const void* ei) {
    int e = blockIdx.x * 256 + threadIdx.x;
    if (e < EE) {
        int d = (int)idx_at(ei, (long long)EE + e);
        atomicAdd(&g_deg[d], 1);
    }
}

// pass 1: per-block sums of g_deg
__global__ void k_scan1() {
    int tid = threadIdx.x;
    int i = blockIdx.x * 256 + tid;
    int v = (i < NN) ? g_deg[i] : 0;
#pragma unroll
    for (int o = 16; o; o >>= 1) v += __shfl_down_sync(0xffffffffu, v, o);
    __shared__ int ws[8];
    if ((tid & 31) == 0) ws[tid >> 5] = v;
    __syncthreads();
    if (tid < 8) {
        int s = ws[tid];
#pragma unroll
        for (int o = 4; o; o >>= 1) s += __shfl_down_sync(0xffu, s, o);
        if (tid == 0) g_blk[blockIdx.x] = s;
    }
}

// pass 2: exclusive scan of block sums (single block, 512 threads)
__global__ void k_scan2() {
    __shared__ int s[512];
    int t = threadIdx.x;
    int v = (t < SCAN_BLOCKS) ? g_blk[t] : 0;
    s[t] = v;
    __syncthreads();
    for (int d = 1; d < 512; d <<= 1) {
        int x = (t >= d) ? s[t - d] : 0;
        __syncthreads();
        s[t] += x;
        __syncthreads();
    }
    if (t < SCAN_BLOCKS) g_blkoff[t] = s[t] - v;
    if (t == 511) g_rowptr[NN] = s[511];
}

// pass 3: local exclusive scan + block offset -> rowptr/cursor
__global__ void k_scan3() {
    int tid = threadIdx.x;
    int i = blockIdx.x * 256 + tid;
    int v = (i < NN) ? g_deg[i] : 0;
    int x = v;
#pragma unroll
    for (int o = 1; o < 32; o <<= 1) {
        int y = __shfl_up_sync(0xffffffffu, x, o);
        if ((tid & 31) >= o) x += y;
    }
    __shared__ int ws[8];
    if ((tid & 31) == 31) ws[tid >> 5] = x;
    __syncthreads();
    if (tid < 8) {
        int s = ws[tid];
#pragma unroll
        for (int o = 1; o < 8; o <<= 1) {
            int y = __shfl_up_sync(0xffu, s, o);
            if (tid >= o) s += y;
        }
        ws[tid] = s;   // inclusive warp sums
    }
    __syncthreads();
    int warpoff = (tid >= 32) ? ws[(tid >> 5) - 1] : 0;
    int excl = x - v + warpoff + g_blkoff[blockIdx.x];
    if (i < NN) { g_rowptr[i] = excl; g_cursor[i] = excl; }
}

__global__ void k_dis_cnt(const void* batch) {
    int i = blockIdx.x * 256 + threadIdx.x;
    if (i < NN) {
        g_dis[i] = rsqrtf((float)g_deg[i] + 1.0f);
        int g = (int)idx_at(batch, i);
        atomicAdd(&g_cnt[g], 1.0f);
    }
}

__global__ void k_place(const void* ei) {
    int e = blockIdx.x * 256 + threadIdx.x;
    if (e < EE) {
        int d = (int)idx_at(ei, (long long)EE + e);
        int pos = atomicAdd(&g_cursor[d], 1);
        g_csrc[pos] = (int)idx_at(ei, (long long)e);
    }
}

// ---------------- W prep: split + transpose -> g_wth/g_wtl [n][k] ----------------
__global__ void k_prepw(const float* __restrict__ W) {
    int idx = blockIdx.x * 256 + threadIdx.x;
    if (idx < HH * HH) {
        int k = idx >> 7, n = idx & 127;
        float v = W[idx];                    // W[k][n] row-major
        uint32_t h = f2tf32(v);
        float l = v - __uint_as_float(h);
        g_wth[n * HH + k] = h;
        g_wtl[n * HH + k] = __float_as_uint(l);
    }
}

// ---------------- tensor-core GEMM: xs = dis * ((A[*affine]) @ W) ----------------
// 128x128 tile per block, tf32 3-split (hh + hl + lh), fp32 accumulate.
// smem layout (uint32): Ah[128*36] Al[128*36] Wh[128*36] Wl[128*36] ss[128] tt[128]
#define LDS 36
#define SM_AH 0
#define SM_AL (128 * LDS)
#define SM_WH (2 * 128 * LDS)
#define SM_WL (3 * 128 * LDS)
#define SM_SS (4 * 128 * LDS)
#define SM_TT (4 * 128 * LDS + 128)
#define SMEM_U32 (4 * 128 * LDS + 256)

template<bool AFF>
__global__ void __launch_bounds__(256, 2) k_gemm_tc(const float* __restrict__ Ain) {
    extern __shared__ uint32_t sm[];
    const float* __restrict__ A = AFF ? (const float*)g_h : Ain;
    int tid = threadIdx.x;
    int wid = tid >> 5, lane = tid & 31;
    int wm = wid >> 1, wn = wid & 1;        // 4 x 2 warp grid
    int ly = lane >> 2, lx = lane & 3;
    int rbase = blockIdx.x * 128;

    if (AFF && tid < HH) {
        ((float*)sm)[SM_SS + tid] = g_bns[tid];
        ((float*)sm)[SM_TT + tid] = g_bnt[tid];
    }
    __syncthreads();

    float acc[2][8][4];
#pragma unroll
    for (int mt = 0; mt < 2; mt++)
#pragma unroll
        for (int j = 0; j < 8; j++)
#pragma unroll
            for (int q = 0; q < 4; q++) acc[mt][j][q] = 0.f;

    for (int ch = 0; ch < 4; ch++) {
        int kbase = ch * 32;
        // load A chunk (128x32), affine + split to tf32 hi/lo
#pragma unroll
        for (int i = 0; i < 4; i++) {
            int idx = i * 256 + tid;
            int m = idx >> 3, q = idx & 7;
            int gr = rbase + m;
            float4 v = make_float4(0.f, 0.f, 0.f, 0.f);
            if (gr < NN)
                v = *(const float4*)&A[(size_t)gr * HH + kbase + 4 * q];
            if (AFF) {
                int c0 = kbase + 4 * q;
                const float* ss = (const float*)sm + SM_SS;
                const float* tt = (const float*)sm + SM_TT;
                v.x = fmaf(v.x, ss[c0 + 0], tt[c0 + 0]);
                v.y = fmaf(v.y, ss[c0 + 1], tt[c0 + 1]);
                v.z = fmaf(v.z, ss[c0 + 2], tt[c0 + 2]);
                v.w = fmaf(v.w, ss[c0 + 3], tt[c0 + 3]);
            }
            uint32_t hx = f2tf32(v.x), hy = f2tf32(v.y);
            uint32_t hz = f2tf32(v.z), hw = f2tf32(v.w);
            float lx2 = v.x - __uint_as_float(hx);
            float ly2 = v.y - __uint_as_float(hy);
            float lz2 = v.z - __uint_as_float(hz);
            float lw2 = v.w - __uint_as_float(hw);
            *(uint4*)&sm[SM_AH + m * LDS + 4 * q] = make_uint4(hx, hy, hz, hw);
            *(uint4*)&sm[SM_AL + m * LDS + 4 * q] =
                make_uint4(__float_as_uint(lx2), __float_as_uint(ly2),
                           __float_as_uint(lz2), __float_as_uint(lw2));
        }
        // load W chunk (pre-split, transposed [n][k])
#pragma unroll
        for (int i = 0; i < 4; i++) {
            int idx = i * 256 + tid;
            int n = idx >> 3, q = idx & 7;
            *(uint4*)&sm[SM_WH + n * LDS + 4 * q] =
                *(const uint4*)&g_wth[n * HH + kbase + 4 * q];
            *(uint4*)&sm[SM_WL + n * LDS + 4 * q] =
                *(const uint4*)&g_wtl[n * HH + kbase + 4 * q];
        }
        __syncthreads();

#pragma unroll
        for (int ks = 0; ks < 4; ks++) {
            int koff = ks * 8;
            uint32_t ah[2][4], al[2][4];
#pragma unroll
            for (int mt = 0; mt < 2; mt++) {
                int rm = wm * 32 + mt * 16;
                int base = (rm + ly) * LDS + koff + lx;
                ah[mt][0] = sm[SM_AH + base];
                ah[mt][1] = sm[SM_AH + base + 8 * LDS];
                ah[mt][2] = sm[SM_AH + base + 4];
                ah[mt][3] = sm[SM_AH + base + 8 * LDS + 4];
                al[mt][0] = sm[SM_AL + base];
                al[mt][1] = sm[SM_AL + base + 8 * LDS];
                al[mt][2] = sm[SM_AL + base + 4];
                al[mt][3] = sm[SM_AL + base + 8 * LDS + 4];
            }
#pragma unroll
            for (int j = 0; j < 8; j++) {
                int nb = wn * 64 + 8 * j;
                int bbase = (nb + ly) * LDS + koff + lx;
                uint32_t bh0 = sm[SM_WH + bbase];
                uint32_t bh1 = sm[SM_WH + bbase + 4];
                uint32_t bl0 = sm[SM_WL + bbase];
                uint32_t bl1 = sm[SM_WL + bbase + 4];
#pragma unroll
                for (int mt = 0; mt < 2; mt++) {
                    mma_tf32(acc[mt][j], ah[mt], bh0, bh1);
                    mma_tf32(acc[mt][j], ah[mt], bl0, bl1);
                    mma_tf32(acc[mt][j], al[mt], bh0, bh1);
                }
            }
        }
        __syncthreads();
    }

    // epilogue: xs = dis[r] * acc
#pragma unroll
    for (int mt = 0; mt < 2; mt++) {
        int r0 = rbase + wm * 32 + mt * 16 + ly;
        int r1 = r0 + 8;
        float d0 = (r0 < NN) ? g_dis[r0] : 0.f;
        float d1 = (r1 < NN) ? g_dis[r1] : 0.f;
#pragma unroll
        for (int j = 0; j < 8; j++) {
            int cb = wn * 64 + 8 * j + 2 * lx;
            if (r0 < NN)
                *(float2*)&g_xs[(size_t)r0 * HH + cb] =
                    make_float2(d0 * acc[mt][j][0], d0 * acc[mt][j][1]);
            if (r1 < NN)
                *(float2*)&g_xs[(size_t)r1 * HH + cb] =
                    make_float2(d1 * acc[mt][j][2], d1 * acc[mt][j][3]);
        }
    }
}

// ---------------- aggregation + relu + BN stats (+ pooling on last layer) ----------------
template<bool LAST>
__global__ void __launch_bounds__(256) k_agg(const float* __restrict__ bias,
                                             const void* __restrict__ batch) {
    int tid = threadIdx.x;
    int wid = tid >> 5, lane = tid & 31;
    float4 b4 = ((const float4*)bias)[lane];
    float s0 = 0.f, s1 = 0.f, s2 = 0.f, s3 = 0.f;
    float q0 = 0.f, q1 = 0.f, q2 = 0.f, q3 = 0.f;

    for (long long i = (long long)blockIdx.x * 8 + wid; i < NN;
         i += (long long)gridDim.x * 8) {
        const float4* xsv = (const float4*)g_xs;
        float4 acc = xsv[i * 32 + lane];          // self term
        int e0 = g_rowptr[i], e1 = g_rowptr[i + 1];
        for (int e = e0; e < e1; e++) {
            int s = g_csrc[e];
            float4 v = xsv[(long long)s * 32 + lane];
            acc.x += v.x; acc.y += v.y; acc.z += v.z; acc.w += v.w;
        }
        float d = g_dis[i];
        float4 y;
        y.x = fmaxf(fmaf(d, acc.x, b4.x), 0.f);
        y.y = fmaxf(fmaf(d, acc.y, b4.y), 0.f);
        y.z = fmaxf(fmaf(d, acc.z, b4.z), 0.f);
        y.w = fmaxf(fmaf(d, acc.w, b4.w), 0.f);
        if (!LAST) {
            ((float4*)g_h)[i * 32 + lane] = y;
        } else {
            int g = (int)idx_at(batch, i);
            float* p = &g_pool[g * HH + lane * 4];
            atomicAdd(p + 0, y.x);
            atomicAdd(p + 1, y.y);
            atomicAdd(p + 2, y.z);
            atomicAdd(p + 3, y.w);
        }
        s0 += y.x; s1 += y.y; s2 += y.z; s3 += y.w;
        q0 += y.x * y.x; q1 += y.y * y.y; q2 += y.z * y.z; q3 += y.w * y.w;
    }
    __shared__ float red[2 * HH];
    red[tid] = 0.f;
    __syncthreads();
    atomicAdd(&red[lane * 4 + 0], s0);
    atomicAdd(&red[lane * 4 + 1], s1);
    atomicAdd(&red[lane * 4 + 2], s2);
    atomicAdd(&red[lane * 4 + 3], s3);
    atomicAdd(&red[HH + lane * 4 + 0], q0);
    atomicAdd(&red[HH + lane * 4 + 1], q1);
    atomicAdd(&red[HH + lane * 4 + 2], q2);
    atomicAdd(&red[HH + lane * 4 + 3], q3);
    __syncthreads();
    atomicAdd(&g_stats[tid], red[tid]);
}

// ---------------- BN stats -> affine (also re-zeroes stats for next use) ----------------
__global__ void k_stats(const float* __restrict__ gamma, const float* __restrict__ beta) {
    int f = threadIdx.x;
    float m = g_stats[f] * (1.0f / NN);
    float v = g_stats[HH + f] * (1.0f / NN) - m * m;
    v = fmaxf(v, 0.f);
    float s = gamma[f] * rsqrtf(v + 1e-5f);
    g_bns[f] = s;
    g_bnt[f] = beta[f] - m * s;
    g_stats[f] = 0.f;
    g_stats[HH + f] = 0.f;
}

// ---------------- final head: pooled(BN3) ++ clinical -> linear ----------------
__global__ void k_final(const float* __restrict__ clinical,
                        const float* __restrict__ Wc,
                        const float* __restrict__ bc,
                        float* __restrict__ out) {
    int g = blockIdx.x, j = threadIdx.x;   // 128 threads
    float cnt = fmaxf(g_cnt[g], 1.0f);
    float p = g_pool[g * HH + j] / cnt;
    p = fmaf(p, g_bns[j], g_bnt[j]);
    float r0 = p * Wc[j * KK + 0];
    float r1 = p * Wc[j * KK + 1];
    if (j < CC) {
        float cl = clinical[g * CC + j];
        r0 = fmaf(cl, Wc[(HH + j) * KK + 0], r0);
        r1 = fmaf(cl, Wc[(HH + j) * KK + 1], r1);
    }
    __shared__ float sm0[128], sm1[128];
    sm0[j] = r0; sm1[j] = r1;
    __syncthreads();
    for (int d = 64; d > 0; d >>= 1) {
        if (j < d) { sm0[j] += sm0[j + d]; sm1[j] += sm1[j + d]; }
        __syncthreads();
    }
    if (j == 0) {
        out[g * KK + 0] = sm0[0] + bc[0];
        out[g * KK + 1] = sm1[0] + bc[1];
    }
}

// ---------------- launch ----------------
extern "C" void kernel_launch(void* const* d_in, const int* in_sizes, int n_in,
                              void* d_out, int out_size) {
    const float* x        = (const float*)d_in[0];
    const void*  ei       = d_in[1];
    const void*  batch    = d_in[2];
    const float* clinical = (const float*)d_in[3];
    const float* W1 = (const float*)d_in[4];  const float* b1 = (const float*)d_in[5];
    const float* W2 = (const float*)d_in[6];  const float* b2 = (const float*)d_in[7];
    const float* W3 = (const float*)d_in[8];  const float* b3 = (const float*)d_in[9];
    const float* g1 = (const float*)d_in[10]; const float* be1 = (const float*)d_in[11];
    const float* g2 = (const float*)d_in[12]; const float* be2 = (const float*)d_in[13];
    const float* g3 = (const float*)d_in[14]; const float* be3 = (const float*)d_in[15];
    const float* Wc = (const float*)d_in[16]; const float* bc = (const float*)d_in[17];
    float* out = (float*)d_out;

    const int gemm_blocks = (NN + 127) / 128;   // 782
    const int e_blocks    = (EE + 255) / 256;   // 6250
    const int n_blocks    = (NN + 255) / 256;   // 391
    const size_t gemm_smem = SMEM_U32 * sizeof(uint32_t);

    cudaFuncSetAttribute(k_gemm_tc<false>,
                         cudaFuncAttributeMaxDynamicSharedMemorySize, (int)gemm_smem);
    cudaFuncSetAttribute(k_gemm_tc<true>,
                         cudaFuncAttributeMaxDynamicSharedMemorySize, (int)gemm_smem);

    k_detect<<<1, 32>>>((const int*)ei);
    k_zero_init<<<n_blocks, 256>>>();
    k_hist<<<e_blocks, 256>>>(ei);
    k_scan1<<<SCAN_BLOCKS, 256>>>();
    k_scan2<<<1, 512>>>();
    k_scan3<<<SCAN_BLOCKS, 256>>>();
    k_dis_cnt<<<n_blocks, 256>>>(batch);
    k_place<<<e_blocks, 256>>>(ei);

    // layer 1
    k_prepw<<<64, 256>>>(W1);
    k_gemm_tc<false><<<gemm_blocks, 256, gemm_smem>>>(x);
    k_agg<false><<<1024, 256>>>(b1, batch);
    k_stats<<<1, 128>>>(g1, be1);

    // layer 2
    k_prepw<<<64, 256>>>(W2);
    k_gemm_tc<true><<<gemm_blocks, 256, gemm_smem>>>(nullptr);
    k_agg<false><<<1024, 256>>>(b2, batch);
    k_stats<<<1, 128>>>(g2, be2);

    // layer 3
    k_prepw<<<64, 256>>>(W3);
    k_gemm_tc<true><<<gemm_blocks, 256, gemm_smem>>>(nullptr);
    k_agg<true><<<1024, 256>>>(b3, batch);
    k_stats<<<1, 128>>>(g3, be3);

    k_final<<<GG, 128>>>(clinical, Wc, bc, out);
}

// round 4
// speedup vs baseline: 1.4048x; 1.0972x over previous
#include <cuda_runtime.h>
#include <cuda_fp16.h>
#include <cstdint>

#define NN 100000
#define EE 1600000
#define HH 128
#define GG 256
#define CC 16
#define KK 2

#define SCAN_BLOCKS ((NN + 255) / 256)   // 391

// ---------------- device scratch (static, allowed) ----------------
__device__ __half g_xs16[(size_t)NN * HH]; // dis-scaled transformed features (fp16)
__device__ __half g_h16 [(size_t)NN * HH]; // layer activations (fp16)
__device__ float g_dis[NN];
__device__ int   g_deg[NN];
__device__ int   g_rowptr[NN + 1];
__device__ int   g_cursor[NN];
__device__ int   g_csrc[EE];
__device__ float g_stats[2 * HH];          // [0..127] sum, [128..255] sumsq
__device__ float g_bns[HH];                // BN affine scale
__device__ float g_bnt[HH];                // BN affine shift
__device__ float g_pool[GG * HH];
__device__ float g_cnt[GG];
__device__ int   g_i64;                    // 1 if index tensors are int64
__device__ int   g_blk[SCAN_BLOCKS + 8];
__device__ int   g_blkoff[SCAN_BLOCKS + 8];
__device__ uint32_t g_wth[HH * HH];        // W'^T hi (tf32 bits), layout [n][k]
__device__ uint32_t g_wtl[HH * HH];        // W'^T lo (fp32 bits)
__device__ float g_wr[HH];                 // r[n] = sum_k t[k] * W[k][n]

__device__ __forceinline__ long long idx_at(const void* p, long long i) {
    if (g_i64) return ((const long long*)p)[i];
    return (long long)((const int*)p)[i];
}

__device__ __forceinline__ uint32_t f2tf32(float x) {
    uint32_t r;
    asm("cvt.rna.tf32.f32 %0, %1;" : "=r"(r) : "f"(x));
    return r;
}

__device__ __forceinline__ void mma_tf32(float* c, const uint32_t* a,
                                         uint32_t b0, uint32_t b1) {
    asm volatile(
        "mma.sync.aligned.m16n8k8.row.col.f32.tf32.tf32.f32 "
        "{%0,%1,%2,%3}, {%4,%5,%6,%7}, {%8,%9}, {%0,%1,%2,%3};\n"
        : "+f"(c[0]), "+f"(c[1]), "+f"(c[2]), "+f"(c[3])
        : "r"(a[0]), "r"(a[1]), "r"(a[2]), "r"(a[3]), "r"(b0), "r"(b1));
}

// ---------------- index width detection ----------------
__global__ void k_detect(const int* ei) {
    int lane = threadIdx.x;
    int v = ei[2 * lane + 1] | ei[2 * (lane + 32) + 1] |
            ei[2 * (lane + 64) + 1] | ei[2 * (lane + 96) + 1];
    unsigned m = __ballot_sync(0xffffffffu, v != 0);
    if (lane == 0) g_i64 = (m == 0) ? 1 : 0;
}

// ---------------- init ----------------
__global__ void k_zero_init() {
    int i = blockIdx.x * 256 + threadIdx.x;
    if (i < NN) g_deg[i] = 0;
    if (i < GG * HH) g_pool[i] = 0.f;
    if (i < GG) g_cnt[i] = 0.f;
    if (i < 2 * HH) g_stats[i] = 0.f;
}

// ---------------- CSR build ----------------
__global__ void k_hist(const void* ei) {
    int e = blockIdx.x * 256 + threadIdx.x;
    if (e < EE) {
        int d = (int)idx_at(ei, (long long)EE + e);
        atomicAdd(&g_deg[d], 1);
    }
}

__global__ void k_scan1() {
    int tid = threadIdx.x;
    int i = blockIdx.x * 256 + tid;
    int v = (i < NN) ? g_deg[i] : 0;
#pragma unroll
    for (int o = 16; o; o >>= 1) v += __shfl_down_sync(0xffffffffu, v, o);
    __shared__ int ws[8];
    if ((tid & 31) == 0) ws[tid >> 5] = v;
    __syncthreads();
    if (tid < 8) {
        int s = ws[tid];
#pragma unroll
        for (int o = 4; o; o >>= 1) s += __shfl_down_sync(0xffu, s, o);
        if (tid == 0) g_blk[blockIdx.x] = s;
    }
}

__global__ void k_scan2() {
    __shared__ int s[512];
    int t = threadIdx.x;
    int v = (t < SCAN_BLOCKS) ? g_blk[t] : 0;
    s[t] = v;
    __syncthreads();
    for (int d = 1; d < 512; d <<= 1) {
        int x = (t >= d) ? s[t - d] : 0;
        __syncthreads();
        s[t] += x;
        __syncthreads();
    }
    if (t < SCAN_BLOCKS) g_blkoff[t] = s[t] - v;
    if (t == 511) g_rowptr[NN] = s[511];
}

__global__ void k_scan3() {
    int tid = threadIdx.x;
    int i = blockIdx.x * 256 + tid;
    int v = (i < NN) ? g_deg[i] : 0;
    int x = v;
#pragma unroll
    for (int o = 1; o < 32; o <<= 1) {
        int y = __shfl_up_sync(0xffffffffu, x, o);
        if ((tid & 31) >= o) x += y;
    }
    __shared__ int ws[8];
    if ((tid & 31) == 31) ws[tid >> 5] = x;
    __syncthreads();
    if (tid < 8) {
        int s = ws[tid];
#pragma unroll
        for (int o = 1; o < 8; o <<= 1) {
            int y = __shfl_up_sync(0xffu, s, o);
            if (tid >= o) s += y;
        }
        ws[tid] = s;
    }
    __syncthreads();
    int warpoff = (tid >= 32) ? ws[(tid >> 5) - 1] : 0;
    int excl = x - v + warpoff + g_blkoff[blockIdx.x];
    if (i < NN) { g_rowptr[i] = excl; g_cursor[i] = excl; }
}

__global__ void k_dis_cnt(const void* batch) {
    int i = blockIdx.x * 256 + threadIdx.x;
    if (i < NN) {
        g_dis[i] = rsqrtf((float)g_deg[i] + 1.0f);
        int g = (int)idx_at(batch, i);
        atomicAdd(&g_cnt[g], 1.0f);
    }
}

__global__ void k_place(const void* ei) {
    int e = blockIdx.x * 256 + threadIdx.x;
    if (e < EE) {
        int d = (int)idx_at(ei, (long long)EE + e);
        int pos = atomicAdd(&g_cursor[d], 1);
        g_csrc[pos] = (int)idx_at(ei, (long long)e);
    }
}

// ---------------- W prep ----------------
// layer 1: plain split + transpose; zero r
__global__ void k_prepw1(const float* __restrict__ W) {
    int idx = blockIdx.x * 256 + threadIdx.x;
    if (idx < HH * HH) {
        int k = idx >> 7, n = idx & 127;
        float v = W[idx];
        uint32_t h = f2tf32(v);
        g_wth[n * HH + k] = h;
        g_wtl[n * HH + k] = __float_as_uint(v - __uint_as_float(h));
    }
    if (blockIdx.x == 0 && threadIdx.x < HH) g_wr[threadIdx.x] = 0.f;
}

// layers 2/3: fold BN scale into W rows: W'[k][n] = s[k]*W[k][n]
__global__ void k_prepw_aff(const float* __restrict__ W) {
    int idx = blockIdx.x * 256 + threadIdx.x;
    if (idx < HH * HH) {
        int k = idx >> 7, n = idx & 127;
        float v = W[idx] * g_bns[k];
        uint32_t h = f2tf32(v);
        g_wth[n * HH + k] = h;
        g_wtl[n * HH + k] = __float_as_uint(v - __uint_as_float(h));
    }
}

// r[n] = sum_k t[k] * W[k][n]
__global__ void k_prepr(const float* __restrict__ W) {
    int n = threadIdx.x;
    float r = 0.f;
#pragma unroll 4
    for (int k = 0; k < HH; k++) r = fmaf(g_bnt[k], W[k * HH + n], r);
    g_wr[n] = r;
}

// ---------------- tensor-core GEMM: xs16 = dis * (A @ W' + r) ----------------
// MODE 0: A fp32 (layer 1), 3-split (Ah*Wh + Ah*Wl + Al*Wh)
// MODE 1: A fp16 (g_h16), exact in tf32, 2 MMAs (Ah*Wh + Ah*Wl)
#define LDS 36
#define SM_AH 0
#define SM_AL (128 * LDS)
#define SM_WH (2 * 128 * LDS)
#define SM_WL (3 * 128 * LDS)
#define SMEM_U32 (4 * 128 * LDS)

template<int MODE>
__global__ void __launch_bounds__(256, 2) k_gemm_tc(const float* __restrict__ Ain) {
    extern __shared__ uint32_t sm[];
    int tid = threadIdx.x;
    int wid = tid >> 5, lane = tid & 31;
    int wm = wid >> 1, wn = wid & 1;        // 4 x 2 warp grid
    int ly = lane >> 2, lx = lane & 3;
    int rbase = blockIdx.x * 128;

    float acc[2][8][4];
#pragma unroll
    for (int mt = 0; mt < 2; mt++)
#pragma unroll
        for (int j = 0; j < 8; j++)
#pragma unroll
            for (int q = 0; q < 4; q++) acc[mt][j][q] = 0.f;

    for (int ch = 0; ch < 4; ch++) {
        int kbase = ch * 32;
        // load A chunk (128x32)
#pragma unroll
        for (int i = 0; i < 4; i++) {
            int idx = i * 256 + tid;
            int m = idx >> 3, q = idx & 7;
            int gr = rbase + m;
            if (MODE == 0) {
                float4 v = make_float4(0.f, 0.f, 0.f, 0.f);
                if (gr < NN)
                    v = *(const float4*)&Ain[(size_t)gr * HH + kbase + 4 * q];
                uint32_t hx = f2tf32(v.x), hy = f2tf32(v.y);
                uint32_t hz = f2tf32(v.z), hw = f2tf32(v.w);
                *(uint4*)&sm[SM_AH + m * LDS + 4 * q] = make_uint4(hx, hy, hz, hw);
                *(uint4*)&sm[SM_AL + m * LDS + 4 * q] = make_uint4(
                    __float_as_uint(v.x - __uint_as_float(hx)),
                    __float_as_uint(v.y - __uint_as_float(hy)),
                    __float_as_uint(v.z - __uint_as_float(hz)),
                    __float_as_uint(v.w - __uint_as_float(hw)));
            } else {
                uint2 u = make_uint2(0u, 0u);
                if (gr < NN)
                    u = *(const uint2*)&g_h16[(size_t)gr * HH + kbase + 4 * q];
                float2 f0 = __half22float2(*(__half2*)&u.x);
                float2 f1 = __half22float2(*(__half2*)&u.y);
                *(uint4*)&sm[SM_AH + m * LDS + 4 * q] = make_uint4(
                    __float_as_uint(f0.x), __float_as_uint(f0.y),
                    __float_as_uint(f1.x), __float_as_uint(f1.y));
            }
        }
        // load W chunk (pre-split, transposed [n][k])
#pragma unroll
        for (int i = 0; i < 4; i++) {
            int idx = i * 256 + tid;
            int n = idx >> 3, q = idx & 7;
            *(uint4*)&sm[SM_WH + n * LDS + 4 * q] =
                *(const uint4*)&g_wth[n * HH + kbase + 4 * q];
            *(uint4*)&sm[SM_WL + n * LDS + 4 * q] =
                *(const uint4*)&g_wtl[n * HH + kbase + 4 * q];
        }
        __syncthreads();

#pragma unroll
        for (int ks = 0; ks < 4; ks++) {
            int koff = ks * 8;
            uint32_t ah[2][4], al[2][4];
#pragma unroll
            for (int mt = 0; mt < 2; mt++) {
                int rm = wm * 32 + mt * 16;
                int base = (rm + ly) * LDS + koff + lx;
                ah[mt][0] = sm[SM_AH + base];
                ah[mt][1] = sm[SM_AH + base + 8 * LDS];
                ah[mt][2] = sm[SM_AH + base + 4];
                ah[mt][3] = sm[SM_AH + base + 8 * LDS + 4];
                if (MODE == 0) {
                    al[mt][0] = sm[SM_AL + base];
                    al[mt][1] = sm[SM_AL + base + 8 * LDS];
                    al[mt][2] = sm[SM_AL + base + 4];
                    al[mt][3] = sm[SM_AL + base + 8 * LDS + 4];
                }
            }
#pragma unroll
            for (int j = 0; j < 8; j++) {
                int nb = wn * 64 + 8 * j;
                int bbase = (nb + ly) * LDS + koff + lx;
                uint32_t bh0 = sm[SM_WH + bbase];
                uint32_t bh1 = sm[SM_WH + bbase + 4];
                uint32_t bl0 = sm[SM_WL + bbase];
                uint32_t bl1 = sm[SM_WL + bbase + 4];
#pragma unroll
                for (int mt = 0; mt < 2; mt++) {
                    mma_tf32(acc[mt][j], ah[mt], bh0, bh1);
                    mma_tf32(acc[mt][j], ah[mt], bl0, bl1);
                    if (MODE == 0) mma_tf32(acc[mt][j], al[mt], bh0, bh1);
                }
            }
        }
        __syncthreads();
    }

    // epilogue: xs16 = dis[r] * (acc + wr)
#pragma unroll
    for (int mt = 0; mt < 2; mt++) {
        int r0 = rbase + wm * 32 + mt * 16 + ly;
        int r1 = r0 + 8;
        float d0 = (r0 < NN) ? g_dis[r0] : 0.f;
        float d1 = (r1 < NN) ? g_dis[r1] : 0.f;
#pragma unroll
        for (int j = 0; j < 8; j++) {
            int cb = wn * 64 + 8 * j + 2 * lx;
            float ra = g_wr[cb], rb = g_wr[cb + 1];
            if (r0 < NN) {
                __half2 o = __floats2half2_rn(d0 * (acc[mt][j][0] + ra),
                                              d0 * (acc[mt][j][1] + rb));
                *(__half2*)&g_xs16[(size_t)r0 * HH + cb] = o;
            }
            if (r1 < NN) {
                __half2 o = __floats2half2_rn(d1 * (acc[mt][j][2] + ra),
                                              d1 * (acc[mt][j][3] + rb));
                *(__half2*)&g_xs16[(size_t)r1 * HH + cb] = o;
            }
        }
    }
}

// ---------------- aggregation + relu + BN stats (+ pooling on last layer) ----------------
template<bool LAST>
__global__ void __launch_bounds__(256) k_agg(const float* __restrict__ bias,
                                             const void* __restrict__ batch) {
    int tid = threadIdx.x;
    int wid = tid >> 5, lane = tid & 31;
    float4 b4 = ((const float4*)bias)[lane];
    float s0 = 0.f, s1 = 0.f, s2 = 0.f, s3 = 0.f;
    float q0 = 0.f, q1 = 0.f, q2 = 0.f, q3 = 0.f;
    const uint2* xsv = (const uint2*)g_xs16;

    for (long long i = (long long)blockIdx.x * 8 + wid; i < NN;
         i += (long long)gridDim.x * 8) {
        uint2 u = xsv[i * 32 + lane];                 // self term
        float2 a0 = __half22float2(*(__half2*)&u.x);
        float2 a1 = __half22float2(*(__half2*)&u.y);
        float acx = a0.x, acy = a0.y, acz = a1.x, acw = a1.y;
        int e0 = g_rowptr[i], e1 = g_rowptr[i + 1];
        for (int e = e0; e < e1; e++) {
            int s = g_csrc[e];
            uint2 v = xsv[(long long)s * 32 + lane];
            float2 v0 = __half22float2(*(__half2*)&v.x);
            float2 v1 = __half22float2(*(__half2*)&v.y);
            acx += v0.x; acy += v0.y; acz += v1.x; acw += v1.y;
        }
        float d = g_dis[i];
        float yx = fmaxf(fmaf(d, acx, b4.x), 0.f);
        float yy = fmaxf(fmaf(d, acy, b4.y), 0.f);
        float yz = fmaxf(fmaf(d, acz, b4.z), 0.f);
        float yw = fmaxf(fmaf(d, acw, b4.w), 0.f);
        if (!LAST) {
            uint2 o;
            *(__half2*)&o.x = __floats2half2_rn(yx, yy);
            *(__half2*)&o.y = __floats2half2_rn(yz, yw);
            ((uint2*)g_h16)[i * 32 + lane] = o;
        } else {
            int g = (int)idx_at(batch, i);
            float* p = &g_pool[g * HH + lane * 4];
            atomicAdd(p + 0, yx);
            atomicAdd(p + 1, yy);
            atomicAdd(p + 2, yz);
            atomicAdd(p + 3, yw);
        }
        s0 += yx; s1 += yy; s2 += yz; s3 += yw;
        q0 += yx * yx; q1 += yy * yy; q2 += yz * yz; q3 += yw * yw;
    }
    __shared__ float red[2 * HH];
    red[tid] = 0.f;
    __syncthreads();
    atomicAdd(&red[lane * 4 + 0], s0);
    atomicAdd(&red[lane * 4 + 1], s1);
    atomicAdd(&red[lane * 4 + 2], s2);
    atomicAdd(&red[lane * 4 + 3], s3);
    atomicAdd(&red[HH + lane * 4 + 0], q0);
    atomicAdd(&red[HH + lane * 4 + 1], q1);
    atomicAdd(&red[HH + lane * 4 + 2], q2);
    atomicAdd(&red[HH + lane * 4 + 3], q3);
    __syncthreads();
    atomicAdd(&g_stats[tid], red[tid]);
}

// ---------------- BN stats -> affine (re-zeroes stats for next use) ----------------
__global__ void k_stats(const float* __restrict__ gamma, const float* __restrict__ beta) {
    int f = threadIdx.x;
    float m = g_stats[f] * (1.0f / NN);
    float v = g_stats[HH + f] * (1.0f / NN) - m * m;
    v = fmaxf(v, 0.f);
    float s = gamma[f] * rsqrtf(v + 1e-5f);
    g_bns[f] = s;
    g_bnt[f] = beta[f] - m * s;
    g_stats[f] = 0.f;
    g_stats[HH + f] = 0.f;
}

// ---------------- final head: pooled(BN3) ++ clinical -> linear ----------------
__global__ void k_final(const float* __restrict__ clinical,
                        const float* __restrict__ Wc,
                        const float* __restrict__ bc,
                        float* __restrict__ out) {
    int g = blockIdx.x, j = threadIdx.x;   // 128 threads
    float cnt = fmaxf(g_cnt[g], 1.0f);
    float p = g_pool[g * HH + j] / cnt;
    p = fmaf(p, g_bns[j], g_bnt[j]);
    float r0 = p * Wc[j * KK + 0];
    float r1 = p * Wc[j * KK + 1];
    if (j < CC) {
        float cl = clinical[g * CC + j];
        r0 = fmaf(cl, Wc[(HH + j) * KK + 0], r0);
        r1 = fmaf(cl, Wc[(HH + j) * KK + 1], r1);
    }
    __shared__ float sm0[128], sm1[128];
    sm0[j] = r0; sm1[j] = r1;
    __syncthreads();
    for (int d = 64; d > 0; d >>= 1) {
        if (j < d) { sm0[j] += sm0[j + d]; sm1[j] += sm1[j + d]; }
        __syncthreads();
    }
    if (j == 0) {
        out[g * KK + 0] = sm0[0] + bc[0];
        out[g * KK + 1] = sm1[0] + bc[1];
    }
}

// ---------------- launch ----------------
extern "C" void kernel_launch(void* const* d_in, const int* in_sizes, int n_in,
                              void* d_out, int out_size) {
    const float* x        = (const float*)d_in[0];
    const void*  ei       = d_in[1];
    const void*  batch    = d_in[2];
    const float* clinical = (const float*)d_in[3];
    const float* W1 = (const float*)d_in[4];  const float* b1 = (const float*)d_in[5];
    const float* W2 = (const float*)d_in[6];  const float* b2 = (const float*)d_in[7];
    const float* W3 = (const float*)d_in[8];  const float* b3 = (const float*)d_in[9];
    const float* g1 = (const float*)d_in[10]; const float* be1 = (const float*)d_in[11];
    const float* g2 = (const float*)d_in[12]; const float* be2 = (const float*)d_in[13];
    const float* g3 = (const float*)d_in[14]; const float* be3 = (const float*)d_in[15];
    const float* Wc = (const float*)d_in[16]; const float* bc = (const float*)d_in[17];
    float* out = (float*)d_out;

    const int gemm_blocks = (NN + 127) / 128;   // 782
    const int e_blocks    = (EE + 255) / 256;   // 6250
    const int n_blocks    = (NN + 255) / 256;   // 391
    const size_t gemm_smem = SMEM_U32 * sizeof(uint32_t);

    cudaFuncSetAttribute(k_gemm_tc<0>,
                         cudaFuncAttributeMaxDynamicSharedMemorySize, (int)gemm_smem);
    cudaFuncSetAttribute(k_gemm_tc<1>,
                         cudaFuncAttributeMaxDynamicSharedMemorySize, (int)gemm_smem);

    k_detect<<<1, 32>>>((const int*)ei);
    k_zero_init<<<n_blocks, 256>>>();
    k_hist<<<e_blocks, 256>>>(ei);
    k_scan1<<<SCAN_BLOCKS, 256>>>();
    k_scan2<<<1, 512>>>();
    k_scan3<<<SCAN_BLOCKS, 256>>>();
    k_dis_cnt<<<n_blocks, 256>>>(batch);
    k_place<<<e_blocks, 256>>>(ei);

    // layer 1
    k_prepw1<<<64, 256>>>(W1);
    k_gemm_tc<0><<<gemm_blocks, 256, gemm_smem>>>(x);
    k_agg<false><<<1024, 256>>>(b1, batch);
    k_stats<<<1, 128>>>(g1, be1);

    // layer 2
    k_prepw_aff<<<64, 256>>>(W2);
    k_prepr<<<1, 128>>>(W2);
    k_gemm_tc<1><<<gemm_blocks, 256, gemm_smem>>>(nullptr);
    k_agg<false><<<1024, 256>>>(b2, batch);
    k_stats<<<1, 128>>>(g2, be2);

    // layer 3
    k_prepw_aff<<<64, 256>>>(W3);
    k_prepr<<<1, 128>>>(W3);
    k_gemm_tc<1><<<gemm_blocks, 256, gemm_smem>>>(nullptr);
    k_agg<true><<<1024, 256>>>(b3, batch);
    k_stats<<<1, 128>>>(g3, be3);

    k_final<<<GG, 128>>>(clinical, Wc, bc, out);
}

// round 5
// speedup vs baseline: 1.4314x; 1.0190x over previous
#include <cuda_runtime.h>
#include <cuda_fp16.h>
#include <cstdint>

#define NN 100000
#define EE 1600000
#define HH 128
#define GG 256
#define CC 16
#define KK 2

#define SCAN_BLOCKS ((NN + 255) / 256)   // 391
#define AGG_BLOCKS 1024

// ---------------- device scratch (static, allowed) ----------------
__device__ __half g_xs16[(size_t)NN * HH]; // dis-scaled transformed features (fp16)
__device__ __half g_h16 [(size_t)NN * HH]; // layer activations (fp16)
__device__ float g_dis[NN];
__device__ int   g_deg[NN];
__device__ int   g_rowptr[NN + 1];
__device__ int   g_cursor[NN];
__device__ int   g_csrc[EE];
__device__ float g_stats[2 * HH];          // [0..127] sum, [128..255] sumsq
__device__ float g_bns[HH];                // BN affine scale
__device__ float g_bnt[HH];                // BN affine shift
__device__ float g_pool[GG * HH];
__device__ float g_cnt[GG];
__device__ int   g_i64;                    // 1 if index tensors are int64
__device__ int   g_blk[SCAN_BLOCKS + 8];
__device__ int   g_blkoff[SCAN_BLOCKS + 8];
__device__ uint32_t g_wth[HH * HH];        // W'^T hi (tf32 bits), layout [n][k]
__device__ uint32_t g_wtl[HH * HH];        // W'^T lo (fp32 bits)
__device__ float g_wr[HH];                 // r[n] = sum_k t[k] * W[k][n]
__device__ unsigned g_arr;                 // arrival counter for agg epilogue

__device__ __forceinline__ long long idx_at(const void* p, long long i) {
    if (g_i64) return ((const long long*)p)[i];
    return (long long)((const int*)p)[i];
}

__device__ __forceinline__ uint32_t f2tf32(float x) {
    uint32_t r;
    asm("cvt.rna.tf32.f32 %0, %1;" : "=r"(r) : "f"(x));
    return r;
}

__device__ __forceinline__ void mma_tf32(float* c, const uint32_t* a,
                                         uint32_t b0, uint32_t b1) {
    asm volatile(
        "mma.sync.aligned.m16n8k8.row.col.f32.tf32.tf32.f32 "
        "{%0,%1,%2,%3}, {%4,%5,%6,%7}, {%8,%9}, {%0,%1,%2,%3};\n"
        : "+f"(c[0]), "+f"(c[1]), "+f"(c[2]), "+f"(c[3])
        : "r"(a[0]), "r"(a[1]), "r"(a[2]), "r"(a[3]), "r"(b0), "r"(b1));
}

// ---------------- init (+ index width detection in block 0) ----------------
__global__ void k_init(const int* ei) {
    int i = blockIdx.x * 256 + threadIdx.x;
    if (blockIdx.x == 0 && threadIdx.x < 32) {
        int lane = threadIdx.x;
        int v = ei[2 * lane + 1] | ei[2 * (lane + 32) + 1] |
                ei[2 * (lane + 64) + 1] | ei[2 * (lane + 96) + 1];
        unsigned m = __ballot_sync(0xffffffffu, v != 0);
        if (lane == 0) g_i64 = (m == 0) ? 1 : 0;
    }
    if (i < NN) g_deg[i] = 0;
    if (i < GG * HH) g_pool[i] = 0.f;
    if (i < GG) g_cnt[i] = 0.f;
    if (i < 2 * HH) g_stats[i] = 0.f;
    if (i == 0) g_arr = 0u;
}

// ---------------- CSR build ----------------
__global__ void k_hist(const void* ei) {
    int e = blockIdx.x * 256 + threadIdx.x;
    if (e < EE) {
        int d = (int)idx_at(ei, (long long)EE + e);
        atomicAdd(&g_deg[d], 1);
    }
}

__global__ void k_scan1() {
    int tid = threadIdx.x;
    int i = blockIdx.x * 256 + tid;
    int v = (i < NN) ? g_deg[i] : 0;
#pragma unroll
    for (int o = 16; o; o >>= 1) v += __shfl_down_sync(0xffffffffu, v, o);
    __shared__ int ws[8];
    if ((tid & 31) == 0) ws[tid >> 5] = v;
    __syncthreads();
    if (tid < 8) {
        int s = ws[tid];
#pragma unroll
        for (int o = 4; o; o >>= 1) s += __shfl_down_sync(0xffu, s, o);
        if (tid == 0) g_blk[blockIdx.x] = s;
    }
}

__global__ void k_scan2() {
    __shared__ int s[512];
    int t = threadIdx.x;
    int v = (t < SCAN_BLOCKS) ? g_blk[t] : 0;
    s[t] = v;
    __syncthreads();
    for (int d = 1; d < 512; d <<= 1) {
        int x = (t >= d) ? s[t - d] : 0;
        __syncthreads();
        s[t] += x;
        __syncthreads();
    }
    if (t < SCAN_BLOCKS) g_blkoff[t] = s[t] - v;
    if (t == 511) g_rowptr[NN] = s[511];
}

// local scan + block offset -> rowptr/cursor; also dis + graph node counts
__global__ void k_scan3(const void* batch) {
    int tid = threadIdx.x;
    int i = blockIdx.x * 256 + tid;
    int v = (i < NN) ? g_deg[i] : 0;
    int x = v;
#pragma unroll
    for (int o = 1; o < 32; o <<= 1) {
        int y = __shfl_up_sync(0xffffffffu, x, o);
        if ((tid & 31) >= o) x += y;
    }
    __shared__ int ws[8];
    if ((tid & 31) == 31) ws[tid >> 5] = x;
    __syncthreads();
    if (tid < 8) {
        int s = ws[tid];
#pragma unroll
        for (int o = 1; o < 8; o <<= 1) {
            int y = __shfl_up_sync(0xffu, s, o);
            if (tid >= o) s += y;
        }
        ws[tid] = s;
    }
    __syncthreads();
    int warpoff = (tid >= 32) ? ws[(tid >> 5) - 1] : 0;
    int excl = x - v + warpoff + g_blkoff[blockIdx.x];
    if (i < NN) {
        g_rowptr[i] = excl;
        g_cursor[i] = excl;
        g_dis[i] = rsqrtf((float)v + 1.0f);
        int g = (int)idx_at(batch, i);
        atomicAdd(&g_cnt[g], 1.0f);
    }
}

__global__ void k_place(const void* ei) {
    int e = blockIdx.x * 256 + threadIdx.x;
    if (e < EE) {
        int d = (int)idx_at(ei, (long long)EE + e);
        int pos = atomicAdd(&g_cursor[d], 1);
        g_csrc[pos] = (int)idx_at(ei, (long long)e);
    }
}

// ---------------- W prep ----------------
// layer 1: plain split + transpose; zero r
__global__ void k_prepw1(const float* __restrict__ W) {
    int idx = blockIdx.x * 256 + threadIdx.x;
    if (idx < HH * HH) {
        int k = idx >> 7, n = idx & 127;
        float v = W[idx];
        uint32_t h = f2tf32(v);
        g_wth[n * HH + k] = h;
        g_wtl[n * HH + k] = __float_as_uint(v - __uint_as_float(h));
    }
    if (blockIdx.x == 0 && threadIdx.x < HH) g_wr[threadIdx.x] = 0.f;
}

// layers 2/3: fold BN scale into W rows + compute r; grid = 65 blocks
__global__ void k_prepw_aff_r(const float* __restrict__ W) {
    if (blockIdx.x < 64) {
        int idx = blockIdx.x * 256 + threadIdx.x;
        int k = idx >> 7, n = idx & 127;
        float v = W[idx] * g_bns[k];
        uint32_t h = f2tf32(v);
        g_wth[n * HH + k] = h;
        g_wtl[n * HH + k] = __float_as_uint(v - __uint_as_float(h));
    } else if (threadIdx.x < HH) {
        int n = threadIdx.x;
        float r = 0.f;
#pragma unroll 4
        for (int k = 0; k < HH; k++) r = fmaf(g_bnt[k], W[k * HH + n], r);
        g_wr[n] = r;
    }
}

// ---------------- tensor-core GEMM: xs16 = dis * (A @ W' + r) ----------------
// MODE 0: A fp32 (layer 1), 3-split (Ah*Wh + Ah*Wl + Al*Wh)
// MODE 1: A fp16 (g_h16), exact in tf32, 2 MMAs (Ah*Wh + Ah*Wl)
#define LDS 36
#define SM_AH 0
#define SM_AL (128 * LDS)
#define SM_WH (2 * 128 * LDS)
#define SM_WL (3 * 128 * LDS)
#define SMEM_U32 (4 * 128 * LDS)

template<int MODE>
__global__ void __launch_bounds__(256, 2) k_gemm_tc(const float* __restrict__ Ain) {
    extern __shared__ uint32_t sm[];
    int tid = threadIdx.x;
    int wid = tid >> 5, lane = tid & 31;
    int wm = wid >> 1, wn = wid & 1;        // 4 x 2 warp grid
    int ly = lane >> 2, lx = lane & 3;
    int rbase = blockIdx.x * 128;

    float acc[2][8][4];
#pragma unroll
    for (int mt = 0; mt < 2; mt++)
#pragma unroll
        for (int j = 0; j < 8; j++)
#pragma unroll
            for (int q = 0; q < 4; q++) acc[mt][j][q] = 0.f;

    for (int ch = 0; ch < 4; ch++) {
        int kbase = ch * 32;
        // load A chunk (128x32)
#pragma unroll
        for (int i = 0; i < 4; i++) {
            int idx = i * 256 + tid;
            int m = idx >> 3, q = idx & 7;
            int gr = rbase + m;
            if (MODE == 0) {
                float4 v = make_float4(0.f, 0.f, 0.f, 0.f);
                if (gr < NN)
                    v = *(const float4*)&Ain[(size_t)gr * HH + kbase + 4 * q];
                uint32_t hx = f2tf32(v.x), hy = f2tf32(v.y);
                uint32_t hz = f2tf32(v.z), hw = f2tf32(v.w);
                *(uint4*)&sm[SM_AH + m * LDS + 4 * q] = make_uint4(hx, hy, hz, hw);
                *(uint4*)&sm[SM_AL + m * LDS + 4 * q] = make_uint4(
                    __float_as_uint(v.x - __uint_as_float(hx)),
                    __float_as_uint(v.y - __uint_as_float(hy)),
                    __float_as_uint(v.z - __uint_as_float(hz)),
                    __float_as_uint(v.w - __uint_as_float(hw)));
            } else {
                uint2 u = make_uint2(0u, 0u);
                if (gr < NN)
                    u = *(const uint2*)&g_h16[(size_t)gr * HH + kbase + 4 * q];
                float2 f0 = __half22float2(*(__half2*)&u.x);
                float2 f1 = __half22float2(*(__half2*)&u.y);
                *(uint4*)&sm[SM_AH + m * LDS + 4 * q] = make_uint4(
                    __float_as_uint(f0.x), __float_as_uint(f0.y),
                    __float_as_uint(f1.x), __float_as_uint(f1.y));
            }
        }
        // load W chunk (pre-split, transposed [n][k])
#pragma unroll
        for (int i = 0; i < 4; i++) {
            int idx = i * 256 + tid;
            int n = idx >> 3, q = idx & 7;
            *(uint4*)&sm[SM_WH + n * LDS + 4 * q] =
                *(const uint4*)&g_wth[n * HH + kbase + 4 * q];
            *(uint4*)&sm[SM_WL + n * LDS + 4 * q] =
                *(const uint4*)&g_wtl[n * HH + kbase + 4 * q];
        }
        __syncthreads();

#pragma unroll
        for (int ks = 0; ks < 4; ks++) {
            int koff = ks * 8;
            uint32_t ah[2][4], al[2][4];
#pragma unroll
            for (int mt = 0; mt < 2; mt++) {
                int rm = wm * 32 + mt * 16;
                int base = (rm + ly) * LDS + koff + lx;
                ah[mt][0] = sm[SM_AH + base];
                ah[mt][1] = sm[SM_AH + base + 8 * LDS];
                ah[mt][2] = sm[SM_AH + base + 4];
                ah[mt][3] = sm[SM_AH + base + 8 * LDS + 4];
                if (MODE == 0) {
                    al[mt][0] = sm[SM_AL + base];
                    al[mt][1] = sm[SM_AL + base + 8 * LDS];
                    al[mt][2] = sm[SM_AL + base + 4];
                    al[mt][3] = sm[SM_AL + base + 8 * LDS + 4];
                }
            }
#pragma unroll
            for (int j = 0; j < 8; j++) {
                int nb = wn * 64 + 8 * j;
                int bbase = (nb + ly) * LDS + koff + lx;
                uint32_t bh0 = sm[SM_WH + bbase];
                uint32_t bh1 = sm[SM_WH + bbase + 4];
                uint32_t bl0 = sm[SM_WL + bbase];
                uint32_t bl1 = sm[SM_WL + bbase + 4];
#pragma unroll
                for (int mt = 0; mt < 2; mt++) {
                    mma_tf32(acc[mt][j], ah[mt], bh0, bh1);
                    mma_tf32(acc[mt][j], ah[mt], bl0, bl1);
                    if (MODE == 0) mma_tf32(acc[mt][j], al[mt], bh0, bh1);
                }
            }
        }
        __syncthreads();
    }

    // epilogue: xs16 = dis[r] * (acc + wr)
#pragma unroll
    for (int mt = 0; mt < 2; mt++) {
        int r0 = rbase + wm * 32 + mt * 16 + ly;
        int r1 = r0 + 8;
        float d0 = (r0 < NN) ? g_dis[r0] : 0.f;
        float d1 = (r1 < NN) ? g_dis[r1] : 0.f;
#pragma unroll
        for (int j = 0; j < 8; j++) {
            int cb = wn * 64 + 8 * j + 2 * lx;
            float ra = g_wr[cb], rb = g_wr[cb + 1];
            if (r0 < NN) {
                __half2 o = __floats2half2_rn(d0 * (acc[mt][j][0] + ra),
                                              d0 * (acc[mt][j][1] + rb));
                *(__half2*)&g_xs16[(size_t)r0 * HH + cb] = o;
            }
            if (r1 < NN) {
                __half2 o = __floats2half2_rn(d1 * (acc[mt][j][2] + ra),
                                              d1 * (acc[mt][j][3] + rb));
                *(__half2*)&g_xs16[(size_t)r1 * HH + cb] = o;
            }
        }
    }
}

// ------- aggregation + relu + BN stats (+ pooling on last layer) + BN solve -------
#define ACC4(u0, u1) { \
    float2 t0 = __half22float2(*(__half2*)&(u0)); \
    float2 t1 = __half22float2(*(__half2*)&(u1)); \
    acx += t0.x; acy += t0.y; acz += t1.x; acw += t1.y; }

template<bool LAST>
__global__ void __launch_bounds__(256) k_agg(const float* __restrict__ bias,
                                             const void* __restrict__ batch,
                                             const float* __restrict__ gamma,
                                             const float* __restrict__ beta) {
    int tid = threadIdx.x;
    int wid = tid >> 5, lane = tid & 31;
    float4 b4 = ((const float4*)bias)[lane];
    float s0 = 0.f, s1 = 0.f, s2 = 0.f, s3 = 0.f;
    float q0 = 0.f, q1 = 0.f, q2 = 0.f, q3 = 0.f;
    const uint2* xsv = (const uint2*)g_xs16;

    for (long long i = (long long)blockIdx.x * 8 + wid; i < NN;
         i += (long long)AGG_BLOCKS * 8) {
        uint2 u = xsv[i * 32 + lane];                 // self term
        float acx, acy, acz, acw;
        {
            float2 a0 = __half22float2(*(__half2*)&u.x);
            float2 a1 = __half22float2(*(__half2*)&u.y);
            acx = a0.x; acy = a0.y; acz = a1.x; acw = a1.y;
        }
        int e0 = g_rowptr[i], e1 = g_rowptr[i + 1];
        int e = e0;
        // unrolled by 4: batch independent gathers for MLP
        for (; e + 4 <= e1; e += 4) {
            int sA = g_csrc[e], sB = g_csrc[e + 1];
            int sC = g_csrc[e + 2], sD = g_csrc[e + 3];
            uint2 vA = xsv[(long long)sA * 32 + lane];
            uint2 vB = xsv[(long long)sB * 32 + lane];
            uint2 vC = xsv[(long long)sC * 32 + lane];
            uint2 vD = xsv[(long long)sD * 32 + lane];
            ACC4(vA.x, vA.y); ACC4(vB.x, vB.y);
            ACC4(vC.x, vC.y); ACC4(vD.x, vD.y);
        }
        for (; e < e1; e++) {
            int s = g_csrc[e];
            uint2 v = xsv[(long long)s * 32 + lane];
            ACC4(v.x, v.y);
        }
        float d = g_dis[i];
        float yx = fmaxf(fmaf(d, acx, b4.x), 0.f);
        float yy = fmaxf(fmaf(d, acy, b4.y), 0.f);
        float yz = fmaxf(fmaf(d, acz, b4.z), 0.f);
        float yw = fmaxf(fmaf(d, acw, b4.w), 0.f);
        if (!LAST) {
            uint2 o;
            *(__half2*)&o.x = __floats2half2_rn(yx, yy);
            *(__half2*)&o.y = __floats2half2_rn(yz, yw);
            ((uint2*)g_h16)[i * 32 + lane] = o;
        } else {
            int g = (int)idx_at(batch, i);
            float* p = &g_pool[g * HH + lane * 4];
            atomicAdd(p + 0, yx);
            atomicAdd(p + 1, yy);
            atomicAdd(p + 2, yz);
            atomicAdd(p + 3, yw);
        }
        s0 += yx; s1 += yy; s2 += yz; s3 += yw;
        q0 += yx * yx; q1 += yy * yy; q2 += yz * yz; q3 += yw * yw;
    }
    __shared__ float red[2 * HH];
    red[tid] = 0.f;
    __syncthreads();
    atomicAdd(&red[lane * 4 + 0], s0);
    atomicAdd(&red[lane * 4 + 1], s1);
    atomicAdd(&red[lane * 4 + 2], s2);
    atomicAdd(&red[lane * 4 + 3], s3);
    atomicAdd(&red[HH + lane * 4 + 0], q0);
    atomicAdd(&red[HH + lane * 4 + 1], q1);
    atomicAdd(&red[HH + lane * 4 + 2], q2);
    atomicAdd(&red[HH + lane * 4 + 3], q3);
    __syncthreads();
    atomicAdd(&g_stats[tid], red[tid]);
    // last-block epilogue: BN stats -> affine (replaces k_stats launch)
    __threadfence();
    __syncthreads();
    __shared__ int isLast;
    if (tid == 0)
        isLast = (atomicAdd(&g_arr, 1u) == (unsigned)(AGG_BLOCKS - 1)) ? 1 : 0;
    __syncthreads();
    if (isLast) {
        if (tid < HH) {
            float m = g_stats[tid] * (1.0f / NN);
            float v = g_stats[HH + tid] * (1.0f / NN) - m * m;
            v = fmaxf(v, 0.f);
            float s = gamma[tid] * rsqrtf(v + 1e-5f);
            g_bns[tid] = s;
            g_bnt[tid] = beta[tid] - m * s;
            g_stats[tid] = 0.f;
            g_stats[HH + tid] = 0.f;
        }
        if (tid == 0) g_arr = 0u;
    }
}

// ---------------- final head: pooled(BN3) ++ clinical -> linear ----------------
__global__ void k_final(const float* __restrict__ clinical,
                        const float* __restrict__ Wc,
                        const float* __restrict__ bc,
                        float* __restrict__ out) {
    int g = blockIdx.x, j = threadIdx.x;   // 128 threads
    float cnt = fmaxf(g_cnt[g], 1.0f);
    float p = g_pool[g * HH + j] / cnt;
    p = fmaf(p, g_bns[j], g_bnt[j]);
    float r0 = p * Wc[j * KK + 0];
    float r1 = p * Wc[j * KK + 1];
    if (j < CC) {
        float cl = clinical[g * CC + j];
        r0 = fmaf(cl, Wc[(HH + j) * KK + 0], r0);
        r1 = fmaf(cl, Wc[(HH + j) * KK + 1], r1);
    }
    __shared__ float sm0[128], sm1[128];
    sm0[j] = r0; sm1[j] = r1;
    __syncthreads();
    for (int d = 64; d > 0; d >>= 1) {
        if (j < d) { sm0[j] += sm0[j + d]; sm1[j] += sm1[j + d]; }
        __syncthreads();
    }
    if (j == 0) {
        out[g * KK + 0] = sm0[0] + bc[0];
        out[g * KK + 1] = sm1[0] + bc[1];
    }
}

// ---------------- launch ----------------
extern "C" void kernel_launch(void* const* d_in, const int* in_sizes, int n_in,
                              void* d_out, int out_size) {
    const float* x        = (const float*)d_in[0];
    const void*  ei       = d_in[1];
    const void*  batch    = d_in[2];
    const float* clinical = (const float*)d_in[3];
    const float* W1 = (const float*)d_in[4];  const float* b1 = (const float*)d_in[5];
    const float* W2 = (const float*)d_in[6];  const float* b2 = (const float*)d_in[7];
    const float* W3 = (const float*)d_in[8];  const float* b3 = (const float*)d_in[9];
    const float* g1 = (const float*)d_in[10]; const float* be1 = (const float*)d_in[11];
    const float* g2 = (const float*)d_in[12]; const float* be2 = (const float*)d_in[13];
    const float* g3 = (const float*)d_in[14]; const float* be3 = (const float*)d_in[15];
    const float* Wc = (const float*)d_in[16]; const float* bc = (const float*)d_in[17];
    float* out = (float*)d_out;

    const int gemm_blocks = (NN + 127) / 128;   // 782
    const int e_blocks    = (EE + 255) / 256;   // 6250
    const int n_blocks    = (NN + 255) / 256;   // 391
    const size_t gemm_smem = SMEM_U32 * sizeof(uint32_t);

    cudaFuncSetAttribute(k_gemm_tc<0>,
                         cudaFuncAttributeMaxDynamicSharedMemorySize, (int)gemm_smem);
    cudaFuncSetAttribute(k_gemm_tc<1>,
                         cudaFuncAttributeMaxDynamicSharedMemorySize, (int)gemm_smem);

    k_init<<<n_blocks, 256>>>((const int*)ei);
    k_hist<<<e_blocks, 256>>>(ei);
    k_scan1<<<SCAN_BLOCKS, 256>>>();
    k_scan2<<<1, 512>>>();
    k_scan3<<<SCAN_BLOCKS, 256>>>(batch);
    k_place<<<e_blocks, 256>>>(ei);

    // layer 1
    k_prepw1<<<64, 256>>>(W1);
    k_gemm_tc<0><<<gemm_blocks, 256, gemm_smem>>>(x);
    k_agg<false><<<AGG_BLOCKS, 256>>>(b1, batch, g1, be1);

    // layer 2
    k_prepw_aff_r<<<65, 256>>>(W2);
    k_gemm_tc<1><<<gemm_blocks, 256, gemm_smem>>>(nullptr);
    k_agg<false><<<AGG_BLOCKS, 256>>>(b2, batch, g2, be2);

    // layer 3
    k_prepw_aff_r<<<65, 256>>>(W3);
    k_gemm_tc<1><<<gemm_blocks, 256, gemm_smem>>>(nullptr);
    k_agg<true><<<AGG_BLOCKS, 256>>>(b3, batch, g3, be3);

    k_final<<<GG, 128>>>(clinical, Wc, bc, out);
}